// round 5
// baseline (speedup 1.0000x reference)
#include <cuda_runtime.h>
#include <cstdint>

// Problem constants (fixed by the reference).
#define BB 256
#define NN 512
#define N_ITERS 300
#define POWER_ITERS 30

// 256 MB scratch for Q = gamma^2 * C^T C, one [512,512] fp32 matrix per batch.
__device__ float g_Q[(size_t)BB * NN * NN];

// ---------------------------------------------------------------------------
// Kernel 1: Q[b] = gamma[b]^2 * C[b]^T C[b]
// Tiled SIMT fp32 GEMM: 128x128 tile, K-chunk 16, 256 threads, 8x8 per thread.
// ---------------------------------------------------------------------------
#define GT 128
#define GK 16

__global__ __launch_bounds__(256, 2)
void qgemm_kernel(const float* __restrict__ C, const float* __restrict__ gamma) {
    const int b  = blockIdx.z;
    const int ti = blockIdx.y;
    const int tj = blockIdx.x;
    const int I = ti * GT;
    const int J = tj * GT;

    const float* Cb = C + (size_t)b * NN * NN;
    float*       Qb = g_Q + (size_t)b * NN * NN;

    __shared__ float As[GK][GT];
    __shared__ float Bs[GK][GT];

    const int tid = threadIdx.x;          // 0..255
    const int tx  = tid & 15;             // 0..15 -> column group
    const int ty  = tid >> 4;             // 0..15 -> row group

    float acc[8][8];
#pragma unroll
    for (int i = 0; i < 8; i++)
#pragma unroll
        for (int j = 0; j < 8; j++) acc[i][j] = 0.0f;

    for (int k0 = 0; k0 < NN; k0 += GK) {
        // Load 16x128 A-tile (cols I..) and B-tile (cols J..): 512 float4 each,
        // 2 float4 per thread, fully coalesced.
#pragma unroll
        for (int L = 0; L < 2; L++) {
            const int f  = tid + L * 256;
            const int kk = f >> 5;
            const int c4 = f & 31;
            const float4 va = *(const float4*)(Cb + (size_t)(k0 + kk) * NN + I + c4 * 4);
            const float4 vb = *(const float4*)(Cb + (size_t)(k0 + kk) * NN + J + c4 * 4);
            *(float4*)&As[kk][c4 * 4] = va;
            *(float4*)&Bs[kk][c4 * 4] = vb;
        }
        __syncthreads();

#pragma unroll
        for (int k = 0; k < GK; k++) {
            float a[8], bb[8];
            *(float4*)&a[0]  = *(const float4*)&As[k][ty * 4];
            *(float4*)&a[4]  = *(const float4*)&As[k][64 + ty * 4];
            *(float4*)&bb[0] = *(const float4*)&Bs[k][tx * 4];
            *(float4*)&bb[4] = *(const float4*)&Bs[k][64 + tx * 4];
#pragma unroll
            for (int i = 0; i < 8; i++)
#pragma unroll
                for (int j = 0; j < 8; j++)
                    acc[i][j] = fmaf(a[i], bb[j], acc[i][j]);
        }
        __syncthreads();
    }

    const float gm = gamma[b];
    const float g2 = gm * gm;

#pragma unroll
    for (int ii = 0; ii < 8; ii++) {
        const int row = I + ((ii < 4) ? (ty * 4 + ii) : (64 + ty * 4 + (ii - 4)));
        float4 o0 = make_float4(acc[ii][0] * g2, acc[ii][1] * g2,
                                acc[ii][2] * g2, acc[ii][3] * g2);
        float4 o1 = make_float4(acc[ii][4] * g2, acc[ii][5] * g2,
                                acc[ii][6] * g2, acc[ii][7] * g2);
        *(float4*)(Qb + (size_t)row * NN + J + tx * 4)      = o0;
        *(float4*)(Qb + (size_t)row * NN + J + 64 + tx * 4) = o1;
    }
}

// ---------------------------------------------------------------------------
// Kernel 2: persistent per-batch solver (power iteration + FISTA), 512 threads.
// Thread t owns component t of all vectors. Q streamed from DRAM each matvec.
// ---------------------------------------------------------------------------

__device__ __forceinline__ float dot4(float4 a, float4 b) {
    return fmaf(a.x, b.x, fmaf(a.y, b.y, fmaf(a.z, b.z, a.w * b.w)));
}

// Block matvec: shz = Q * shy. 16 warps, 32 rows/warp, rows processed in pairs
// (8 outstanding LDG.128 per warp). y cached in registers per lane.
__device__ __forceinline__ void matvec512(const float4* __restrict__ Qb4,
                                          const float4* shy4, float* shz,
                                          int warp, int lane) {
    const float4 y0 = shy4[lane];
    const float4 y1 = shy4[32 + lane];
    const float4 y2 = shy4[64 + lane];
    const float4 y3 = shy4[96 + lane];
    const float4* qp = Qb4 + (size_t)(warp * 32) * 128;
#pragma unroll 1
    for (int rr = 0; rr < 32; rr += 2) {
        const float4* qa = qp + (size_t)rr * 128;
        float4 a0 = __ldg(qa + lane);
        float4 a1 = __ldg(qa + 32 + lane);
        float4 a2 = __ldg(qa + 64 + lane);
        float4 a3 = __ldg(qa + 96 + lane);
        float4 b0 = __ldg(qa + 128 + lane);
        float4 b1 = __ldg(qa + 160 + lane);
        float4 b2 = __ldg(qa + 192 + lane);
        float4 b3 = __ldg(qa + 224 + lane);
        float acc0 = dot4(a0, y0) + dot4(a1, y1) + dot4(a2, y2) + dot4(a3, y3);
        float acc1 = dot4(b0, y0) + dot4(b1, y1) + dot4(b2, y2) + dot4(b3, y3);
#pragma unroll
        for (int o = 16; o; o >>= 1) {
            acc0 += __shfl_xor_sync(0xffffffffu, acc0, o);
            acc1 += __shfl_xor_sync(0xffffffffu, acc1, o);
        }
        if (lane == 0) {
            shz[warp * 32 + rr]     = acc0;
            shz[warp * 32 + rr + 1] = acc1;
        }
    }
}

// Block-wide sum of a float2, broadcast to all 512 threads.
__device__ __forceinline__ float2 bsum2(float2 v, float2* sred2, int tid) {
#pragma unroll
    for (int o = 16; o; o >>= 1) {
        v.x += __shfl_xor_sync(0xffffffffu, v.x, o);
        v.y += __shfl_xor_sync(0xffffffffu, v.y, o);
    }
    if ((tid & 31) == 0) sred2[tid >> 5] = v;
    __syncthreads();
    if (tid < 32) {
        float2 x = (tid < 16) ? sred2[tid] : make_float2(0.0f, 0.0f);
#pragma unroll
        for (int o = 8; o; o >>= 1) {
            x.x += __shfl_xor_sync(0xffffffffu, x.x, o);
            x.y += __shfl_xor_sync(0xffffffffu, x.y, o);
        }
        if (tid == 0) sred2[0] = x;
    }
    __syncthreads();
    const float2 r = sred2[0];
    __syncthreads();  // protect sred2 reuse
    return r;
}

__device__ __forceinline__ float bsum(float v, float2* sred2, int tid) {
    return bsum2(make_float2(v, 0.0f), sred2, tid).x;
}

// Exact Euclidean projection onto the simplex via Michelot's active-set
// iteration: theta is the same value the sort-based reference computes.
__device__ __forceinline__ float project_simplex(float vv, float2* sred2, int tid) {
    float theta = (bsum(vv, sred2, tid) - 1.0f) * (1.0f / (float)NN);
    for (int it = 0; it < NN; ++it) {
        const bool act = vv > theta;
        float2 sk = bsum2(make_float2(act ? vv : 0.0f, act ? 1.0f : 0.0f), sred2, tid);
        if (sk.y < 0.5f) break;                 // defensive; cannot happen
        const float tn = (sk.x - 1.0f) / sk.y;
        if (tn <= theta) break;                 // fixed point (exact) or fp round
        theta = tn;
    }
    return fmaxf(vv - theta, 0.0f);
}

__global__ __launch_bounds__(512, 2)
void solve_kernel(const float* __restrict__ rets, float* __restrict__ out) {
    const int b    = blockIdx.x;
    const int tid  = threadIdx.x;
    const int lane = tid & 31;
    const int warp = tid >> 5;

    const float4* Qb4 = (const float4*)(g_Q + (size_t)b * NN * NN);

    __shared__ float4 shy4[NN / 4];
    __shared__ float  shz[NN];
    __shared__ float2 sred2[16];
    float* shy = (float*)shy4;

    const float ret = rets[(size_t)b * NN + tid];

    // ---- power iteration for lambda_max(Q) ----
    float v = rsqrtf((float)NN);  // v0 = 1/sqrt(N)
    for (int it = 0; it < POWER_ITERS; ++it) {
        shy[tid] = v;
        __syncthreads();
        matvec512(Qb4, shy4, shz, warp, lane);
        __syncthreads();
        const float z  = shz[tid];
        const float ss = bsum(z * z, sred2, tid);
        v = z / (sqrtf(ss) + 1e-12f);
    }
    // lam = v^T Q v
    shy[tid] = v;
    __syncthreads();
    matvec512(Qb4, shy4, shz, warp, lane);
    __syncthreads();
    const float lam = bsum(v * shz[tid], sred2, tid);
    const float eta = 1.0f / (2.0f * lam + 1e-8f);

    // ---- FISTA ----
    float w = 1.0f / (float)NN;
    float y = w;
    float t = 1.0f;
    for (int it = 0; it < N_ITERS; ++it) {
        shy[tid] = y;
        __syncthreads();
        matvec512(Qb4, shy4, shz, warp, lane);
        __syncthreads();
        const float g  = 2.0f * shz[tid] - ret;
        const float vv = y - eta * g;
        const float wn = project_simplex(vv, sred2, tid);
        const float tn = 0.5f * (1.0f + sqrtf(1.0f + 4.0f * t * t));
        const float cf = (t - 1.0f) / tn;
        y = wn + cf * (wn - w);
        w = wn;
        t = tn;
    }

    out[(size_t)b * NN + tid] = w;
}

// ---------------------------------------------------------------------------
// Launch
// ---------------------------------------------------------------------------
extern "C" void kernel_launch(void* const* d_in, const int* in_sizes, int n_in,
                              void* d_out, int out_size) {
    // Identify inputs by element count (rets: 256*512, covmat_sqrt: 256*512*512,
    // gamma: 256) so we are robust to ordering.
    const float* rets = nullptr;
    const float* cov  = nullptr;
    const float* gam  = nullptr;
    for (int i = 0; i < n_in; i++) {
        if (in_sizes[i] == BB * NN)       rets = (const float*)d_in[i];
        else if (in_sizes[i] == BB)       gam  = (const float*)d_in[i];
        else                              cov  = (const float*)d_in[i];
    }
    float* out = (float*)d_out;

    dim3 ggrid(NN / GT, NN / GT, BB);   // 4 x 4 x 256
    qgemm_kernel<<<ggrid, 256>>>(cov, gam);
    solve_kernel<<<BB, NN>>>(rets, out);
    (void)out_size;
}

// round 7
// speedup vs baseline: 1.8181x; 1.8181x over previous
#include <cuda_runtime.h>
#include <cstdint>

// Problem constants (fixed by the reference).
#define BB 256
#define NN 512
#define N_ITERS 300
#define POWER_ITERS 30

#define NT 16              // 32x32 tiles per dimension (512/32)
#define NTILES 136         // NT*(NT+1)/2 lower-triangular tiles
#define TILE_FLOATS 1024   // 32*32

// Packed lower-triangular Q (symmetric): per batch, 136 contiguous 32x32 fp32
// tiles, tile (I,J), I>=J, at linear index p = I*(I+1)/2 + J.  ~143 MB total.
__device__ float g_Qp[(size_t)BB * NTILES * TILE_FLOATS];

// ---------------------------------------------------------------------------
// Kernel 1: Q[b] = gamma[b]^2 * C[b]^T C[b], lower 128x128 blocks only,
// written as packed 32x32 tiles. 256 threads, 8x8 per thread, K-chunk 16.
// ---------------------------------------------------------------------------
#define GT 128
#define GK 16

__global__ __launch_bounds__(256, 2)
void qgemm_kernel(const float* __restrict__ C, const float* __restrict__ gamma) {
    const int b  = blockIdx.z;
    // Map blockIdx.x (0..9) -> lower-triangular 128-block (TI >= TJ).
    int TI = (int)((sqrtf(8.0f * blockIdx.x + 1.0f) - 1.0f) * 0.5f);
    while ((TI + 1) * (TI + 2) / 2 <= (int)blockIdx.x) TI++;
    while (TI * (TI + 1) / 2 > (int)blockIdx.x) TI--;
    const int TJ = blockIdx.x - TI * (TI + 1) / 2;
    const int I = TI * GT;
    const int J = TJ * GT;

    const float* Cb = C + (size_t)b * NN * NN;

    __shared__ float As[GK][GT];
    __shared__ float Bs[GK][GT];

    const int tid = threadIdx.x;          // 0..255
    const int tx  = tid & 15;             // column group
    const int ty  = tid >> 4;             // row group

    float acc[8][8];
#pragma unroll
    for (int i = 0; i < 8; i++)
#pragma unroll
        for (int j = 0; j < 8; j++) acc[i][j] = 0.0f;

    for (int k0 = 0; k0 < NN; k0 += GK) {
#pragma unroll
        for (int L = 0; L < 2; L++) {
            const int f  = tid + L * 256;
            const int kk = f >> 5;
            const int c4 = f & 31;
            const float4 va = *(const float4*)(Cb + (size_t)(k0 + kk) * NN + I + c4 * 4);
            const float4 vb = *(const float4*)(Cb + (size_t)(k0 + kk) * NN + J + c4 * 4);
            *(float4*)&As[kk][c4 * 4] = va;
            *(float4*)&Bs[kk][c4 * 4] = vb;
        }
        __syncthreads();

#pragma unroll
        for (int k = 0; k < GK; k++) {
            float a[8], bb[8];
            *(float4*)&a[0]  = *(const float4*)&As[k][ty * 4];
            *(float4*)&a[4]  = *(const float4*)&As[k][64 + ty * 4];
            *(float4*)&bb[0] = *(const float4*)&Bs[k][tx * 4];
            *(float4*)&bb[4] = *(const float4*)&Bs[k][64 + tx * 4];
#pragma unroll
            for (int i = 0; i < 8; i++)
#pragma unroll
                for (int j = 0; j < 8; j++)
                    acc[i][j] = fmaf(a[i], bb[j], acc[i][j]);
        }
        __syncthreads();
    }

    const float gm = gamma[b];
    const float g2 = gm * gm;
    float* Qpb = g_Qp + (size_t)b * NTILES * TILE_FLOATS;

    // Epilogue: scatter into packed 32x32 tiles, predicate gI >= gJ.
#pragma unroll
    for (int ii = 0; ii < 8; ii++) {
        const int r  = (ii < 4) ? (ty * 4 + ii) : (64 + ty * 4 + (ii - 4));
        const int gI = TI * 4 + (r >> 5);
        const int rr = r & 31;
#pragma unroll
        for (int g = 0; g < 2; g++) {
            const int c  = g * 64 + tx * 4;
            const int gJ = TJ * 4 + (c >> 5);
            if (gI >= gJ) {
                const int pidx = gI * (gI + 1) / 2 + gJ;
                float4 o = make_float4(acc[ii][g * 4 + 0] * g2, acc[ii][g * 4 + 1] * g2,
                                       acc[ii][g * 4 + 2] * g2, acc[ii][g * 4 + 3] * g2);
                *(float4*)(Qpb + (size_t)pidx * TILE_FLOATS + rr * 32 + (c & 31)) = o;
            }
        }
    }
}

// ---------------------------------------------------------------------------
// Kernel 2: persistent per-batch solver, symmetric packed matvec.
// ---------------------------------------------------------------------------

__device__ __forceinline__ float dot4(float4 a, float4 b) {
    return fmaf(a.x, b.x, fmaf(a.y, b.y, fmaf(a.z, b.z, a.w * b.w)));
}

// z = Q*y using packed lower tiles. Deterministic: per-tile partials go to
// fixed slots, combined in fixed order. Returns z[tid].
// slot layout: slot[(Iblk*16 + k)*32 + r] = contribution to row block Iblk,
// row r, from contributor k (k<=Iblk: tile (Iblk,k) row-product;
// k>Iblk: transpose of tile (k,Iblk)).
__device__ __forceinline__ float matvec_sym(const float4* __restrict__ Qb4,
                                            const float* shy, float* slot,
                                            const uchar2* sIJ, int tid) {
    const int lane = tid & 31;
    const int warp = tid >> 5;
    const int part = lane & 7;   // float4 column group within tile row
    const int rsub = lane >> 3;  // 0..3

    __syncthreads();  // shy written & previous combine finished

    for (int p = warp; p < NTILES; p += 16) {
        const int I = sIJ[p].x;
        const int J = sIJ[p].y;
        const float4* tb = Qb4 + (size_t)p * (TILE_FLOATS / 4);

        float4 v[8];
#pragma unroll
        for (int s = 0; s < 8; s++) v[s] = __ldg(tb + lane + 32 * s);

        const float4 yj = ((const float4*)(shy + J * 32))[part];

        if (I != J) {
            float4 c = make_float4(0.f, 0.f, 0.f, 0.f);
#pragma unroll
            for (int s = 0; s < 8; s++) {
                const int row = rsub + 4 * s;
                float a = dot4(v[s], yj);
                a += __shfl_xor_sync(0xffffffffu, a, 1);
                a += __shfl_xor_sync(0xffffffffu, a, 2);
                a += __shfl_xor_sync(0xffffffffu, a, 4);
                if (part == 0) slot[(I * 16 + J) * 32 + row] = a;
                const float yi = shy[I * 32 + row];
                c.x = fmaf(v[s].x, yi, c.x);
                c.y = fmaf(v[s].y, yi, c.y);
                c.z = fmaf(v[s].z, yi, c.z);
                c.w = fmaf(v[s].w, yi, c.w);
            }
            // Sum columns over the 4 lanes sharing `part` (rows 0..31 covered).
#pragma unroll
            for (int o = 8; o <= 16; o <<= 1) {
                c.x += __shfl_xor_sync(0xffffffffu, c.x, o);
                c.y += __shfl_xor_sync(0xffffffffu, c.y, o);
                c.z += __shfl_xor_sync(0xffffffffu, c.z, o);
                c.w += __shfl_xor_sync(0xffffffffu, c.w, o);
            }
            if (lane < 8) {
                float* d = &slot[(J * 16 + I) * 32 + part * 4];
                d[0] = c.x; d[1] = c.y; d[2] = c.z; d[3] = c.w;
            }
        } else {
            // Diagonal tile: row products only.
#pragma unroll
            for (int s = 0; s < 8; s++) {
                const int row = rsub + 4 * s;
                float a = dot4(v[s], yj);
                a += __shfl_xor_sync(0xffffffffu, a, 1);
                a += __shfl_xor_sync(0xffffffffu, a, 2);
                a += __shfl_xor_sync(0xffffffffu, a, 4);
                if (part == 0) slot[(I * 16 + I) * 32 + row] = a;
            }
        }
    }

    __syncthreads();  // all slots written

    const int Iq = tid >> 5;
    const int r  = tid & 31;
    float z = 0.0f;
#pragma unroll
    for (int k = 0; k < 16; k++) z += slot[(Iq * 16 + k) * 32 + r];
    return z;
}

// Block-wide sum of a float2, broadcast to all 512 threads.
__device__ __forceinline__ float2 bsum2(float2 v, float2* sred2, int tid) {
#pragma unroll
    for (int o = 16; o; o >>= 1) {
        v.x += __shfl_xor_sync(0xffffffffu, v.x, o);
        v.y += __shfl_xor_sync(0xffffffffu, v.y, o);
    }
    if ((tid & 31) == 0) sred2[tid >> 5] = v;
    __syncthreads();
    if (tid < 32) {
        float2 x = (tid < 16) ? sred2[tid] : make_float2(0.0f, 0.0f);
#pragma unroll
        for (int o = 8; o; o >>= 1) {
            x.x += __shfl_xor_sync(0xffffffffu, x.x, o);
            x.y += __shfl_xor_sync(0xffffffffu, x.y, o);
        }
        if (tid == 0) sred2[0] = x;
    }
    __syncthreads();
    const float2 r = sred2[0];
    __syncthreads();
    return r;
}

__device__ __forceinline__ float bsum(float v, float2* sred2, int tid) {
    return bsum2(make_float2(v, 0.0f), sred2, tid).x;
}

// Exact Euclidean projection onto the simplex (Michelot fixed point; same
// theta as the sort-based reference).
__device__ __forceinline__ float project_simplex(float vv, float2* sred2, int tid) {
    float theta = (bsum(vv, sred2, tid) - 1.0f) * (1.0f / (float)NN);
    for (int it = 0; it < NN; ++it) {
        const bool act = vv > theta;
        float2 sk = bsum2(make_float2(act ? vv : 0.0f, act ? 1.0f : 0.0f), sred2, tid);
        if (sk.y < 0.5f) break;
        const float tn = (sk.x - 1.0f) / sk.y;
        if (tn <= theta) break;
        theta = tn;
    }
    return fmaxf(vv - theta, 0.0f);
}

__global__ __launch_bounds__(512, 2)
void solve_kernel(const float* __restrict__ rets, float* __restrict__ out) {
    const int b   = blockIdx.x;
    const int tid = threadIdx.x;

    const float4* Qb4 = (const float4*)(g_Qp + (size_t)b * NTILES * TILE_FLOATS);

    __shared__ float  slot[16 * 16 * 32];  // 32 KB partials
    __shared__ float  shy[NN];
    __shared__ float2 sred2[16];
    __shared__ uchar2 sIJ[NTILES];

    if (tid < NTILES) {
        int I = (int)((sqrtf(8.0f * tid + 1.0f) - 1.0f) * 0.5f);
        while ((I + 1) * (I + 2) / 2 <= tid) I++;
        while (I * (I + 1) / 2 > tid) I--;
        sIJ[tid] = make_uchar2((unsigned char)I, (unsigned char)(tid - I * (I + 1) / 2));
    }

    const float ret = rets[(size_t)b * NN + tid];

    // ---- power iteration for lambda_max(Q) ----
    float v = rsqrtf((float)NN);
    for (int it = 0; it < POWER_ITERS; ++it) {
        shy[tid] = v;
        const float z  = matvec_sym(Qb4, shy, slot, sIJ, tid);
        const float ss = bsum(z * z, sred2, tid);
        v = z / (sqrtf(ss) + 1e-12f);
    }
    shy[tid] = v;
    {
        const float z   = matvec_sym(Qb4, shy, slot, sIJ, tid);
        const float lam = bsum(v * z, sred2, tid);
        const float eta = 1.0f / (2.0f * lam + 1e-8f);

        // ---- FISTA ----
        float w = 1.0f / (float)NN;
        float y = w;
        float t = 1.0f;
        for (int it = 0; it < N_ITERS; ++it) {
            shy[tid] = y;
            const float z2 = matvec_sym(Qb4, shy, slot, sIJ, tid);
            const float g  = 2.0f * z2 - ret;
            const float vv = y - eta * g;
            const float wn = project_simplex(vv, sred2, tid);
            const float tn = 0.5f * (1.0f + sqrtf(1.0f + 4.0f * t * t));
            const float cf = (t - 1.0f) / tn;
            y = wn + cf * (wn - w);
            w = wn;
            t = tn;
        }
        out[(size_t)b * NN + tid] = w;
    }
}

// ---------------------------------------------------------------------------
// Launch
// ---------------------------------------------------------------------------
extern "C" void kernel_launch(void* const* d_in, const int* in_sizes, int n_in,
                              void* d_out, int out_size) {
    const float* rets = nullptr;
    const float* cov  = nullptr;
    const float* gam  = nullptr;
    for (int i = 0; i < n_in; i++) {
        if (in_sizes[i] == BB * NN)       rets = (const float*)d_in[i];
        else if (in_sizes[i] == BB)       gam  = (const float*)d_in[i];
        else                              cov  = (const float*)d_in[i];
    }
    float* out = (float*)d_out;

    dim3 ggrid(10, 1, BB);   // lower-triangular 128-blocks x batch
    qgemm_kernel<<<ggrid, 256>>>(cov, gam);
    solve_kernel<<<BB, NN>>>(rets, out);
    (void)out_size;
}